// round 12
// baseline (speedup 1.0000x reference)
#include <cuda_runtime.h>
#include <cuda_bf16.h>
#include <math.h>
#include <stdint.h>

#define S_TOK 4096
#define M_DIM 1024
#define H_DIM 4096
#define E_NUM 8
#define C_CAP 1024
#define KTOP  2

// ---------------- scratch (__device__ globals; referenced ONLY from device code) ----------------
__device__ float d_h[(size_t)E_NUM * C_CAP * H_DIM];          // tf32-rounded activations
__device__ float d_yo[(size_t)E_NUM * C_CAP * M_DIM];
__device__ float d_scores[S_TOK * E_NUM];
__device__ int   d_topk[S_TOK * KTOP];
__device__ float d_gate[S_TOK * KTOP];
__device__ int   d_flat[S_TOK * KTOP];
__device__ int   d_perm[E_NUM * C_CAP];
__device__ float d_me[E_NUM];
__device__ int   d_ce[E_NUM];

__device__ const float* g_x;
__device__ const float* g_wg;
__device__ const float* g_fc1w;
__device__ const float* g_fc1b;
__device__ const float* g_fc2w;
__device__ const float* g_fc2b;

// ---------------- generic-PTX helpers (sm_80+; valid on compute_103) ----------------
__device__ __forceinline__ uint32_t smem_u32(const void* p) {
    uint32_t a;
    asm("{ .reg .u64 t; cvta.to.shared.u64 t, %1; cvt.u32.u64 %0, t; }" : "=r"(a) : "l"(p));
    return a;
}
__device__ __forceinline__ void cpa16(uint32_t dst, const void* src, int src_bytes) {
    asm volatile("cp.async.cg.shared.global [%0], [%1], 16, %2;"
                 :: "r"(dst), "l"(src), "r"(src_bytes) : "memory");
}
#define CP_COMMIT() asm volatile("cp.async.commit_group;" ::: "memory")
#define CP_WAIT(n)  asm volatile("cp.async.wait_group %0;" :: "n"(n) : "memory")
#define LDSM4(r0, r1, r2, r3, addr)                                        \
    asm volatile("ldmatrix.sync.aligned.m8n8.x4.shared.b16 {%0,%1,%2,%3}, [%4];" \
                 : "=r"(r0), "=r"(r1), "=r"(r2), "=r"(r3) : "r"(addr))
#define MMA16808(d, a, b0, b1)                                             \
    asm volatile("mma.sync.aligned.m16n8k8.row.col.f32.tf32.tf32.f32 "     \
                 "{%0,%1,%2,%3}, {%4,%5,%6,%7}, {%8,%9}, {%0,%1,%2,%3};"   \
                 : "+f"((d)[0]), "+f"((d)[1]), "+f"((d)[2]), "+f"((d)[3])  \
                 : "r"((a)[0]), "r"((a)[1]), "r"((a)[2]), "r"((a)[3]),     \
                   "r"(b0), "r"(b1))
__device__ __forceinline__ uint32_t to_tf32(float v) {
    uint32_t r;
    asm("cvt.rna.tf32.f32 %0, %1;" : "=r"(r) : "f"(v));
    return r;
}
__device__ __forceinline__ uint32_t lds_tf32(uint32_t addr) {
    float v;
    asm volatile("ld.shared.f32 %0, [%1];" : "=f"(v) : "r"(addr));
    return to_tf32(v);
}

// ---------------- select: resolve ambiguous inputs by content ----------------
__global__ __launch_bounds__(32) void select_kernel(
    const float* x, const float* fc1b,
    const float* s0, const float* s1,
    const float* b0, const float* b1) {
    int lane = threadIdx.x;
    float sa = 0.f, sb = 0.f, ca = 0.f, cb = 0.f;
    for (int i = lane; i < 8192; i += 32) {
        sa += fabsf(s0[i]);
        sb += fabsf(s1[i]);
        ca += fabsf(b0[i]);
        cb += fabsf(b1[i]);
    }
    #pragma unroll
    for (int off = 16; off; off >>= 1) {
        sa += __shfl_down_sync(0xffffffffu, sa, off);
        sb += __shfl_down_sync(0xffffffffu, sb, off);
        ca += __shfl_down_sync(0xffffffffu, ca, off);
        cb += __shfl_down_sync(0xffffffffu, cb, off);
    }
    if (lane == 0) {
        g_x = x;
        g_fc1b = fc1b;
        if (sa >= sb) { g_wg = s0; g_fc2b = s1; }
        else          { g_wg = s1; g_fc2b = s0; }
        if (ca >= cb) { g_fc1w = b0; g_fc2w = b1; }
        else          { g_fc1w = b1; g_fc2w = b0; }
        for (int e = 0; e < E_NUM; e++) d_ce[e] = 0;
    }
}

// ---------------- gating: one warp per token ----------------
__global__ __launch_bounds__(256) void gate_kernel() {
    const int warp = threadIdx.x >> 5;
    const int lane = threadIdx.x & 31;
    const int s = blockIdx.x * 8 + warp;
    if (s >= S_TOK) return;
    const float* x = g_x;
    const float* wg = g_wg;

    float acc[E_NUM] = {0.f, 0.f, 0.f, 0.f, 0.f, 0.f, 0.f, 0.f};
    const float* xrow = x + (size_t)s * M_DIM;
    for (int k = lane; k < M_DIM; k += 32) {
        float xv = xrow[k];
        const float4* w = (const float4*)(wg + (size_t)k * E_NUM);
        float4 w0 = w[0], w1 = w[1];
        acc[0] += xv * w0.x; acc[1] += xv * w0.y; acc[2] += xv * w0.z; acc[3] += xv * w0.w;
        acc[4] += xv * w1.x; acc[5] += xv * w1.y; acc[6] += xv * w1.z; acc[7] += xv * w1.w;
    }
    #pragma unroll
    for (int off = 16; off; off >>= 1) {
        #pragma unroll
        for (int e = 0; e < E_NUM; e++)
            acc[e] += __shfl_down_sync(0xffffffffu, acc[e], off);
    }
    if (lane == 0) {
        float mx = acc[0];
        #pragma unroll
        for (int e = 1; e < E_NUM; e++) mx = fmaxf(mx, acc[e]);
        float sum = 0.f, sc[E_NUM];
        #pragma unroll
        for (int e = 0; e < E_NUM; e++) { sc[e] = expf(acc[e] - mx); sum += sc[e]; }
        float inv = 1.f / sum;
        #pragma unroll
        for (int e = 0; e < E_NUM; e++) { sc[e] *= inv; d_scores[s * E_NUM + e] = sc[e]; }
        int id0 = 0;
        #pragma unroll
        for (int e = 1; e < E_NUM; e++) if (sc[e] > sc[id0]) id0 = e;
        int id1 = -1;
        float b1 = -1.f;
        #pragma unroll
        for (int e = 0; e < E_NUM; e++) {
            if (e != id0 && sc[e] > b1) { b1 = sc[e]; id1 = e; }
        }
        if (id1 < 0) id1 = (id0 + 1) & 7;
        float v0 = sc[id0], v1 = sc[id1];
        float denom = fmaxf(v0 + v1, 1e-7f);
        d_topk[s * 2 + 0] = id0;
        d_topk[s * 2 + 1] = id1;
        d_gate[s * 2 + 0] = v0 / denom;
        d_gate[s * 2 + 1] = v1 / denom;
        atomicAdd(&d_ce[id0], 1);
    }
}

// ---------------- me[e] ----------------
__global__ __launch_bounds__(256) void me_kernel() {
    int e = blockIdx.x;
    int tid = threadIdx.x;
    float acc = 0.f;
    for (int s = tid; s < S_TOK; s += 256) acc += d_scores[s * E_NUM + e];
    __shared__ float sm[256];
    sm[tid] = acc;
    __syncthreads();
    for (int d = 128; d; d >>= 1) {
        if (tid < d) sm[tid] += sm[tid + d];
        __syncthreads();
    }
    if (tid == 0) d_me[e] = sm[0];
}

// ---------------- routing: 8 warps, one per expert; token-ordered, deterministic ----------------
__global__ __launch_bounds__(256) void route_kernel() {
    const int tid = threadIdx.x;
    const int w = tid >> 5;
    const int lane = tid & 31;
    for (int i = tid; i < E_NUM * C_CAP; i += 256) d_perm[i] = -1;
    __syncthreads();

    const unsigned below = (1u << lane) - 1u;
    int off = 0;
    for (int k = 0; k < KTOP; k++) {
        for (int t0 = 0; t0 < S_TOK; t0 += 32) {
            int s = t0 + lane;
            int e = d_topk[s * 2 + k];
            e = (e < 0) ? 0 : ((e > 7) ? 7 : e);
            unsigned m = __ballot_sync(0xffffffffu, e == w);
            if (e == w) {
                int loc = off + __popc(m & below);
                bool valid = loc < C_CAP;
                int flat = w * C_CAP + (valid ? loc : (C_CAP - 1));
                d_flat[s * 2 + k] = flat;
                if (valid) d_perm[flat] = s;
                else       d_gate[s * 2 + k] = 0.f;
            }
            off += __popc(m);
        }
    }
}

// -------- tf32 GEMM, block 128x256, 512 threads / 16 warps (warp 32x64), 3-stage cp.async --------
// A: [m][k] K-major smem (144B rows); GEMM1 reads RAW x (cvt.rna applied to fragments).
// B: [k][n] smem direct from original weights; fragments via 2 conflict-free LDS + cvt.rna.
#define ROWB_A 144
#define ROWN_B 1056
#define OFF_B  18432              // 128 * 144
#define STAGE_B 52224             // 18432 + 32*1056
template <int PHASE>
__global__ __launch_bounds__(512) void gemm_mma() {
    constexpr int KSEG = (PHASE == 1) ? M_DIM : H_DIM;
    constexpr int NDIM = (PHASE == 1) ? H_DIM : M_DIM;
    constexpr int TPS = KSEG / 32;

    extern __shared__ __align__(16) char smem[];
    __shared__ int sRow[128];

    const int tid = threadIdx.x;
    const int lane = tid & 31;
    const int wid = tid >> 5;       // 0..15
    const int wm = wid >> 2;        // 0..3  (32-row slice)
    const int wn = wid & 3;         // 0..3  (64-col slice)
    const int e = blockIdx.z;
    const int M0 = blockIdx.y * 128;
    const int N0 = blockIdx.x * 256;
    const uint32_t sbase = smem_u32(smem);

    if (PHASE == 1) {
        if (tid < 128) sRow[tid] = d_perm[e * C_CAP + tid + M0];
    }
    __syncthreads();

    const float* A = (PHASE == 1) ? g_x : d_h;         // GEMM1: raw x (cvt in frags)
    const float* W = (PHASE == 1) ? g_fc1w : g_fc2w;   // [e][k][n], raw fp32

    auto issue_stage = [&](int stg, int kt) {
        const int kb = kt * 32;
        uint32_t base = sbase + stg * STAGE_B;
        #pragma unroll
        for (int i = 0; i < 2; i++) {       // A: 128 rows x 8 chunks(16B) = 1024
            int ch = tid + i * 512, r = ch >> 3, c = ch & 7;
            size_t srcoff;
            int bytes = 16;
            if (PHASE == 1) {
                int sr = sRow[r];
                srcoff = (sr >= 0) ? ((size_t)sr * KSEG + kb + c * 4) : 0;
                if (sr < 0) bytes = 0;
            } else {
                srcoff = (size_t)(e * C_CAP + M0 + r) * KSEG + kb + c * 4;
            }
            cpa16(base + r * ROWB_A + c * 16, A + srcoff, bytes);
        }
        #pragma unroll
        for (int i = 0; i < 4; i++) {       // B: 32 k-rows x 64 chunks(16B) = 2048
            int ch = tid + i * 512, r = ch >> 6, c = ch & 63;
            size_t srcoff = (size_t)e * KSEG * NDIM + (size_t)(kb + r) * NDIM + N0 + c * 4;
            cpa16(base + OFF_B + r * ROWN_B + c * 16, W + srcoff, 16);
        }
    };

    float acc[2][8][4];
    #pragma unroll
    for (int mi = 0; mi < 2; mi++)
        #pragma unroll
        for (int ni = 0; ni < 8; ni++)
            #pragma unroll
            for (int q = 0; q < 4; q++) acc[mi][ni][q] = 0.f;

    const int l_r = lane & 15;
    const int l_c = (lane >> 4) * 16;
    const int bq = lane >> 2;       // n offset within n8 block
    const int br = lane & 3;        // k offset within k8 block

    issue_stage(0, 0);
    CP_COMMIT();
    issue_stage(1, 1);
    CP_COMMIT();

    for (int it = 0; it < TPS; it++) {
        if (it + 1 < TPS) CP_WAIT(1);
        else              CP_WAIT(0);
        __syncthreads();

        if (it + 2 < TPS) { issue_stage((it + 2) % 3, it + 2); CP_COMMIT(); }

        uint32_t base = sbase + (it % 3) * STAGE_B;
        #pragma unroll
        for (int kk = 0; kk < 4; kk++) {    // four k8 steps per k32 stage
            // A fragments: 2 m16-blocks via ldsm.x4 (tf32-as-b16-pairs trick)
            uint32_t af[2][4];
            #pragma unroll
            for (int mi = 0; mi < 2; mi++) {
                uint32_t ad = base + (uint32_t)(wm * 32 + mi * 16 + l_r) * ROWB_A
                            + (uint32_t)(kk * 32 + l_c);
                LDSM4(af[mi][0], af[mi][1], af[mi][2], af[mi][3], ad);
                if (PHASE == 1) {
                    #pragma unroll
                    for (int q = 0; q < 4; q++)
                        af[mi][q] = to_tf32(__uint_as_float(af[mi][q]));
                }
            }
            // B fragments from [k][n] tile
            uint32_t bd0 = base + OFF_B + (uint32_t)(kk * 8 + br) * ROWN_B
                         + (uint32_t)(wn * 64 + bq) * 4;
            uint32_t bfr[8][2];
            #pragma unroll
            for (int ni = 0; ni < 8; ni++) {
                bfr[ni][0] = lds_tf32(bd0 + ni * 32);
                bfr[ni][1] = lds_tf32(bd0 + ni * 32 + 4 * ROWN_B);
            }
            #pragma unroll
            for (int mi = 0; mi < 2; mi++)
                #pragma unroll
                for (int ni = 0; ni < 8; ni++)
                    MMA16808(acc[mi][ni], af[mi], bfr[ni][0], bfr[ni][1]);
        }
    }

    // ---- epilogue ----
    const float* bias = (PHASE == 1) ? g_fc1b : g_fc2b;
    #pragma unroll
    for (int mi = 0; mi < 2; mi++) {
        #pragma unroll
        for (int ni = 0; ni < 8; ni++) {
            int c = N0 + wn * 64 + ni * 8 + (lane & 3) * 2;
            float2 bv = *(const float2*)&bias[(size_t)e * NDIM + c];
            int r0 = M0 + wm * 32 + mi * 16 + (lane >> 2);
            #pragma unroll
            for (int h = 0; h < 2; h++) {
                int rg = r0 + h * 8;
                float v0 = acc[mi][ni][h * 2 + 0] + bv.x;
                float v1 = acc[mi][ni][h * 2 + 1] + bv.y;
                if (PHASE == 1) {
                    v0 = fmaxf(v0, 0.f);
                    v1 = fmaxf(v1, 0.f);
                    uint2 t = make_uint2(to_tf32(v0), to_tf32(v1));
                    size_t o = (size_t)(e * C_CAP + rg) * H_DIM + c;
                    *(uint2*)(d_h + o) = t;
                } else {
                    size_t o = (size_t)(e * C_CAP + rg) * M_DIM + c;
                    *(float2*)(d_yo + o) = make_float2(v0, v1);
                }
            }
        }
    }
}

// ---------------- combine ----------------
__global__ __launch_bounds__(256) void combine_kernel(float* __restrict__ out) {
    int s = blockIdx.x;
    int tid = threadIdx.x;
    int f0 = d_flat[s * 2 + 0];
    int f1 = d_flat[s * 2 + 1];
    float g0 = d_gate[s * 2 + 0];
    float g1 = d_gate[s * 2 + 1];
    float4 a = ((const float4*)(d_yo + (size_t)f0 * M_DIM))[tid];
    float4 b = ((const float4*)(d_yo + (size_t)f1 * M_DIM))[tid];
    float4 o;
    o.x = g0 * a.x + g1 * b.x;
    o.y = g0 * a.y + g1 * b.y;
    o.z = g0 * a.z + g1 * b.z;
    o.w = g0 * a.w + g1 * b.w;
    ((float4*)(out + (size_t)s * M_DIM))[tid] = o;
}

// ---------------- l_aux ----------------
__global__ __launch_bounds__(32) void laux_kernel(float* __restrict__ out, int write) {
    if (threadIdx.x == 0 && write) {
        float l = 0.f;
        for (int e = 0; e < E_NUM; e++)
            l += (d_me[e] / (float)S_TOK) * ((float)d_ce[e] / (float)S_TOK);
        out[(size_t)S_TOK * M_DIM] = l * (float)E_NUM;
    }
}

// ---------------- launch ----------------
extern "C" void kernel_launch(void* const* d_in, const int* in_sizes, int n_in,
                              void* d_out, int out_size) {
    long long mx = 0;
    for (int i = 0; i < n_in; i++) if ((long long)in_sizes[i] > mx) mx = in_sizes[i];
    long long div = (mx >= 134217728LL) ? 4 : 1;

    const float *x = 0, *fc1_b = 0;
    const float* big[2] = {0, 0};
    const float* sml[2] = {0, 0};
    int nbig = 0, nsml = 0;
    for (int i = 0; i < n_in; i++) {
        const float* p = (const float*)d_in[i];
        long long n = (long long)in_sizes[i] / div;
        if (n == (long long)S_TOK * M_DIM) x = p;
        else if (n == (long long)E_NUM * H_DIM) fc1_b = p;
        else if (n == (long long)E_NUM * M_DIM * H_DIM) { if (nbig < 2) big[nbig++] = p; }
        else if (n == (long long)M_DIM * E_NUM) { if (nsml < 2) sml[nsml++] = p; }
    }
    if (!x || !fc1_b || nbig < 2 || nsml < 2) {
        x = (const float*)d_in[0];
        sml[0] = (const float*)d_in[1];
        big[0] = (const float*)d_in[2];
        fc1_b = (const float*)d_in[3];
        big[1] = (const float*)d_in[4];
        sml[1] = (const float*)d_in[5];
    }
    float* out = (float*)d_out;

    const int SMEM_DYN = 3 * STAGE_B;  // 156672 B
    cudaFuncSetAttribute(gemm_mma<1>, cudaFuncAttributeMaxDynamicSharedMemorySize, SMEM_DYN);
    cudaFuncSetAttribute(gemm_mma<2>, cudaFuncAttributeMaxDynamicSharedMemorySize, SMEM_DYN);

    select_kernel<<<1, 32>>>(x, fc1_b, sml[0], sml[1], big[0], big[1]);
    gate_kernel<<<S_TOK / 8, 256>>>();
    me_kernel<<<E_NUM, 256>>>();
    route_kernel<<<1, 256>>>();

    {
        dim3 g(H_DIM / 256, C_CAP / 128, E_NUM);  // (16, 8, 8)
        gemm_mma<1><<<g, 512, SMEM_DYN>>>();
    }
    {
        dim3 g(M_DIM / 256, C_CAP / 128, E_NUM);  // (4, 8, 8)
        gemm_mma<2><<<g, 512, SMEM_DYN>>>();
    }

    combine_kernel<<<S_TOK, 256>>>(out);
    laux_kernel<<<1, 32>>>(out, out_size > S_TOK * M_DIM ? 1 : 0);
}

// round 13
// speedup vs baseline: 1.1051x; 1.1051x over previous
#include <cuda_runtime.h>
#include <cuda_bf16.h>
#include <math.h>
#include <stdint.h>

#define S_TOK 4096
#define M_DIM 1024
#define H_DIM 4096
#define E_NUM 8
#define C_CAP 1024
#define KTOP  2

// ---------------- scratch (__device__ globals; referenced ONLY from device code) ----------------
__device__ float d_h[(size_t)E_NUM * C_CAP * H_DIM];          // tf32-rounded activations
__device__ float d_yo[(size_t)E_NUM * C_CAP * M_DIM];
__device__ float d_scores[S_TOK * E_NUM];
__device__ int   d_topk[S_TOK * KTOP];
__device__ float d_gate[S_TOK * KTOP];
__device__ int   d_flat[S_TOK * KTOP];
__device__ int   d_perm[E_NUM * C_CAP];
__device__ float d_me[E_NUM];
__device__ int   d_ce[E_NUM];

__device__ const float* g_x;
__device__ const float* g_wg;
__device__ const float* g_fc1w;
__device__ const float* g_fc1b;
__device__ const float* g_fc2w;
__device__ const float* g_fc2b;

// ---------------- generic-PTX helpers (sm_80+; valid on compute_103) ----------------
__device__ __forceinline__ uint32_t smem_u32(const void* p) {
    uint32_t a;
    asm("{ .reg .u64 t; cvta.to.shared.u64 t, %1; cvt.u32.u64 %0, t; }" : "=r"(a) : "l"(p));
    return a;
}
__device__ __forceinline__ void cpa16(uint32_t dst, const void* src, int src_bytes) {
    asm volatile("cp.async.cg.shared.global [%0], [%1], 16, %2;"
                 :: "r"(dst), "l"(src), "r"(src_bytes) : "memory");
}
#define CP_COMMIT() asm volatile("cp.async.commit_group;" ::: "memory")
#define CP_WAIT(n)  asm volatile("cp.async.wait_group %0;" :: "n"(n) : "memory")
#define LDSM4(r0, r1, r2, r3, addr)                                        \
    asm volatile("ldmatrix.sync.aligned.m8n8.x4.shared.b16 {%0,%1,%2,%3}, [%4];" \
                 : "=r"(r0), "=r"(r1), "=r"(r2), "=r"(r3) : "r"(addr))
#define MMA16808(d, a, b0, b1)                                             \
    asm volatile("mma.sync.aligned.m16n8k8.row.col.f32.tf32.tf32.f32 "     \
                 "{%0,%1,%2,%3}, {%4,%5,%6,%7}, {%8,%9}, {%0,%1,%2,%3};"   \
                 : "+f"((d)[0]), "+f"((d)[1]), "+f"((d)[2]), "+f"((d)[3])  \
                 : "r"((a)[0]), "r"((a)[1]), "r"((a)[2]), "r"((a)[3]),     \
                   "r"(b0), "r"(b1))
__device__ __forceinline__ uint32_t to_tf32(float v) {
    uint32_t r;
    asm("cvt.rna.tf32.f32 %0, %1;" : "=r"(r) : "f"(v));
    return r;
}
__device__ __forceinline__ uint32_t lds_tf32(uint32_t addr) {
    float v;
    asm volatile("ld.shared.f32 %0, [%1];" : "=f"(v) : "r"(addr));
    return to_tf32(v);
}

// ---------------- select: resolve ambiguous inputs by content ----------------
__global__ __launch_bounds__(32) void select_kernel(
    const float* x, const float* fc1b,
    const float* s0, const float* s1,
    const float* b0, const float* b1) {
    int lane = threadIdx.x;
    float sa = 0.f, sb = 0.f, ca = 0.f, cb = 0.f;
    for (int i = lane; i < 8192; i += 32) {
        sa += fabsf(s0[i]);
        sb += fabsf(s1[i]);
        ca += fabsf(b0[i]);
        cb += fabsf(b1[i]);
    }
    #pragma unroll
    for (int off = 16; off; off >>= 1) {
        sa += __shfl_down_sync(0xffffffffu, sa, off);
        sb += __shfl_down_sync(0xffffffffu, sb, off);
        ca += __shfl_down_sync(0xffffffffu, ca, off);
        cb += __shfl_down_sync(0xffffffffu, cb, off);
    }
    if (lane == 0) {
        g_x = x;
        g_fc1b = fc1b;
        if (sa >= sb) { g_wg = s0; g_fc2b = s1; }
        else          { g_wg = s1; g_fc2b = s0; }
        if (ca >= cb) { g_fc1w = b0; g_fc2w = b1; }
        else          { g_fc1w = b1; g_fc2w = b0; }
        for (int e = 0; e < E_NUM; e++) d_ce[e] = 0;
    }
}

// ---------------- gating: one warp per token ----------------
__global__ __launch_bounds__(256) void gate_kernel() {
    const int warp = threadIdx.x >> 5;
    const int lane = threadIdx.x & 31;
    const int s = blockIdx.x * 8 + warp;
    if (s >= S_TOK) return;
    const float* x = g_x;
    const float* wg = g_wg;

    float acc[E_NUM] = {0.f, 0.f, 0.f, 0.f, 0.f, 0.f, 0.f, 0.f};
    const float* xrow = x + (size_t)s * M_DIM;
    for (int k = lane; k < M_DIM; k += 32) {
        float xv = xrow[k];
        const float4* w = (const float4*)(wg + (size_t)k * E_NUM);
        float4 w0 = w[0], w1 = w[1];
        acc[0] += xv * w0.x; acc[1] += xv * w0.y; acc[2] += xv * w0.z; acc[3] += xv * w0.w;
        acc[4] += xv * w1.x; acc[5] += xv * w1.y; acc[6] += xv * w1.z; acc[7] += xv * w1.w;
    }
    #pragma unroll
    for (int off = 16; off; off >>= 1) {
        #pragma unroll
        for (int e = 0; e < E_NUM; e++)
            acc[e] += __shfl_down_sync(0xffffffffu, acc[e], off);
    }
    if (lane == 0) {
        float mx = acc[0];
        #pragma unroll
        for (int e = 1; e < E_NUM; e++) mx = fmaxf(mx, acc[e]);
        float sum = 0.f, sc[E_NUM];
        #pragma unroll
        for (int e = 0; e < E_NUM; e++) { sc[e] = expf(acc[e] - mx); sum += sc[e]; }
        float inv = 1.f / sum;
        #pragma unroll
        for (int e = 0; e < E_NUM; e++) { sc[e] *= inv; d_scores[s * E_NUM + e] = sc[e]; }
        int id0 = 0;
        #pragma unroll
        for (int e = 1; e < E_NUM; e++) if (sc[e] > sc[id0]) id0 = e;
        int id1 = -1;
        float b1 = -1.f;
        #pragma unroll
        for (int e = 0; e < E_NUM; e++) {
            if (e != id0 && sc[e] > b1) { b1 = sc[e]; id1 = e; }
        }
        if (id1 < 0) id1 = (id0 + 1) & 7;
        float v0 = sc[id0], v1 = sc[id1];
        float denom = fmaxf(v0 + v1, 1e-7f);
        d_topk[s * 2 + 0] = id0;
        d_topk[s * 2 + 1] = id1;
        d_gate[s * 2 + 0] = v0 / denom;
        d_gate[s * 2 + 1] = v1 / denom;
        atomicAdd(&d_ce[id0], 1);
    }
}

// ---------------- me[e] ----------------
__global__ __launch_bounds__(256) void me_kernel() {
    int e = blockIdx.x;
    int tid = threadIdx.x;
    float acc = 0.f;
    for (int s = tid; s < S_TOK; s += 256) acc += d_scores[s * E_NUM + e];
    __shared__ float sm[256];
    sm[tid] = acc;
    __syncthreads();
    for (int d = 128; d; d >>= 1) {
        if (tid < d) sm[tid] += sm[tid + d];
        __syncthreads();
    }
    if (tid == 0) d_me[e] = sm[0];
}

// ---------------- routing: smem-staged topk; 8 warps, one per expert; token-ordered ----------------
__global__ __launch_bounds__(256) void route_kernel() {
    const int tid = threadIdx.x;
    const int w = tid >> 5;
    const int lane = tid & 31;
    __shared__ int stopk[S_TOK * KTOP];   // 32 KB: kill the serial-DRAM-latency chain
    for (int i = tid; i < E_NUM * C_CAP; i += 256) d_perm[i] = -1;
    for (int i = tid; i < S_TOK * KTOP; i += 256) stopk[i] = d_topk[i];
    __syncthreads();

    const unsigned below = (1u << lane) - 1u;
    int off = 0;
    for (int k = 0; k < KTOP; k++) {
        for (int t0 = 0; t0 < S_TOK; t0 += 32) {
            int s = t0 + lane;
            int e = stopk[s * 2 + k];
            e = (e < 0) ? 0 : ((e > 7) ? 7 : e);
            unsigned m = __ballot_sync(0xffffffffu, e == w);
            if (e == w) {
                int loc = off + __popc(m & below);
                bool valid = loc < C_CAP;
                int flat = w * C_CAP + (valid ? loc : (C_CAP - 1));
                d_flat[s * 2 + k] = flat;
                if (valid) d_perm[flat] = s;
                else       d_gate[s * 2 + k] = 0.f;
            }
            off += __popc(m);
        }
    }
}

// -------- tf32 GEMM, block 128x256, 256 threads / 8 warps (warp 64x64), 3-stage cp.async --------
// A: [m][k] K-major smem (144B rows); GEMM1 reads RAW x (cvt.rna applied to fragments).
// B: [k][n] smem direct from original weights; fragments via 2 conflict-free LDS + cvt.rna.
#define ROWB_A 144
#define ROWN_B 1056
#define OFF_B  18432              // 128 * 144
#define STAGE_B 52224             // 18432 + 32*1056
template <int PHASE>
__global__ __launch_bounds__(256) void gemm_mma() {
    constexpr int KSEG = (PHASE == 1) ? M_DIM : H_DIM;
    constexpr int NDIM = (PHASE == 1) ? H_DIM : M_DIM;
    constexpr int TPS = KSEG / 32;

    extern __shared__ __align__(16) char smem[];
    __shared__ int sRow[128];

    const int tid = threadIdx.x;
    const int lane = tid & 31;
    const int wid = tid >> 5;
    const int wm = wid >> 2;        // 0..1  (64-row slice)
    const int wn = wid & 3;         // 0..3  (64-col slice)
    const int e = blockIdx.z;
    const int M0 = blockIdx.y * 128;
    const int N0 = blockIdx.x * 256;
    const uint32_t sbase = smem_u32(smem);

    if (PHASE == 1) {
        if (tid < 128) sRow[tid] = d_perm[e * C_CAP + tid + M0];
    }
    __syncthreads();

    const float* A = (PHASE == 1) ? g_x : d_h;         // GEMM1: raw x (cvt in frags)
    const float* W = (PHASE == 1) ? g_fc1w : g_fc2w;   // [e][k][n], raw fp32

    auto issue_stage = [&](int stg, int kt) {
        const int kb = kt * 32;
        uint32_t base = sbase + stg * STAGE_B;
        #pragma unroll
        for (int i = 0; i < 4; i++) {       // A: 128 rows x 8 chunks(16B)
            int ch = tid + i * 256, r = ch >> 3, c = ch & 7;
            size_t srcoff;
            int bytes = 16;
            if (PHASE == 1) {
                int sr = sRow[r];
                srcoff = (sr >= 0) ? ((size_t)sr * KSEG + kb + c * 4) : 0;
                if (sr < 0) bytes = 0;
            } else {
                srcoff = (size_t)(e * C_CAP + M0 + r) * KSEG + kb + c * 4;
            }
            cpa16(base + r * ROWB_A + c * 16, A + srcoff, bytes);
        }
        #pragma unroll
        for (int i = 0; i < 8; i++) {       // B: 32 k-rows x 64 chunks(16B)
            int ch = tid + i * 256, r = ch >> 6, c = ch & 63;
            size_t srcoff = (size_t)e * KSEG * NDIM + (size_t)(kb + r) * NDIM + N0 + c * 4;
            cpa16(base + OFF_B + r * ROWN_B + c * 16, W + srcoff, 16);
        }
    };

    float acc[4][8][4];
    #pragma unroll
    for (int mi = 0; mi < 4; mi++)
        #pragma unroll
        for (int ni = 0; ni < 8; ni++)
            #pragma unroll
            for (int q = 0; q < 4; q++) acc[mi][ni][q] = 0.f;

    const int l_r = lane & 15;
    const int l_c = (lane >> 4) * 16;
    const int bq = lane >> 2;       // n offset within n8 block
    const int br = lane & 3;        // k offset within k8 block

    issue_stage(0, 0);
    CP_COMMIT();
    issue_stage(1, 1);
    CP_COMMIT();

    for (int it = 0; it < TPS; it++) {
        if (it + 1 < TPS) CP_WAIT(1);
        else              CP_WAIT(0);
        __syncthreads();

        if (it + 2 < TPS) { issue_stage((it + 2) % 3, it + 2); CP_COMMIT(); }

        uint32_t base = sbase + (it % 3) * STAGE_B;
        #pragma unroll
        for (int kk = 0; kk < 4; kk++) {    // four k8 steps per k32 stage
            // A fragments: 4 m16-blocks via ldsm.x4 (tf32-as-b16-pairs trick)
            uint32_t af[4][4];
            #pragma unroll
            for (int mi = 0; mi < 4; mi++) {
                uint32_t ad = base + (uint32_t)(wm * 64 + mi * 16 + l_r) * ROWB_A
                            + (uint32_t)(kk * 32 + l_c);
                LDSM4(af[mi][0], af[mi][1], af[mi][2], af[mi][3], ad);
                if (PHASE == 1) {
                    #pragma unroll
                    for (int q = 0; q < 4; q++)
                        af[mi][q] = to_tf32(__uint_as_float(af[mi][q]));
                }
            }
            // B fragments from [k][n] tile
            uint32_t bd0 = base + OFF_B + (uint32_t)(kk * 8 + br) * ROWN_B
                         + (uint32_t)(wn * 64 + bq) * 4;
            uint32_t bfr[8][2];
            #pragma unroll
            for (int ni = 0; ni < 8; ni++) {
                bfr[ni][0] = lds_tf32(bd0 + ni * 32);
                bfr[ni][1] = lds_tf32(bd0 + ni * 32 + 4 * ROWN_B);
            }
            #pragma unroll
            for (int mi = 0; mi < 4; mi++)
                #pragma unroll
                for (int ni = 0; ni < 8; ni++)
                    MMA16808(acc[mi][ni], af[mi], bfr[ni][0], bfr[ni][1]);
        }
    }

    // ---- epilogue ----
    const float* bias = (PHASE == 1) ? g_fc1b : g_fc2b;
    #pragma unroll
    for (int mi = 0; mi < 4; mi++) {
        #pragma unroll
        for (int ni = 0; ni < 8; ni++) {
            int c = N0 + wn * 64 + ni * 8 + (lane & 3) * 2;
            float2 bv = *(const float2*)&bias[(size_t)e * NDIM + c];
            int r0 = M0 + wm * 64 + mi * 16 + (lane >> 2);
            #pragma unroll
            for (int h = 0; h < 2; h++) {
                int rg = r0 + h * 8;
                float v0 = acc[mi][ni][h * 2 + 0] + bv.x;
                float v1 = acc[mi][ni][h * 2 + 1] + bv.y;
                if (PHASE == 1) {
                    v0 = fmaxf(v0, 0.f);
                    v1 = fmaxf(v1, 0.f);
                    uint2 t = make_uint2(to_tf32(v0), to_tf32(v1));
                    size_t o = (size_t)(e * C_CAP + rg) * H_DIM + c;
                    *(uint2*)(d_h + o) = t;
                } else {
                    size_t o = (size_t)(e * C_CAP + rg) * M_DIM + c;
                    *(float2*)(d_yo + o) = make_float2(v0, v1);
                }
            }
        }
    }
}

// ---------------- combine ----------------
__global__ __launch_bounds__(256) void combine_kernel(float* __restrict__ out) {
    int s = blockIdx.x;
    int tid = threadIdx.x;
    int f0 = d_flat[s * 2 + 0];
    int f1 = d_flat[s * 2 + 1];
    float g0 = d_gate[s * 2 + 0];
    float g1 = d_gate[s * 2 + 1];
    float4 a = ((const float4*)(d_yo + (size_t)f0 * M_DIM))[tid];
    float4 b = ((const float4*)(d_yo + (size_t)f1 * M_DIM))[tid];
    float4 o;
    o.x = g0 * a.x + g1 * b.x;
    o.y = g0 * a.y + g1 * b.y;
    o.z = g0 * a.z + g1 * b.z;
    o.w = g0 * a.w + g1 * b.w;
    ((float4*)(out + (size_t)s * M_DIM))[tid] = o;
}

// ---------------- l_aux ----------------
__global__ __launch_bounds__(32) void laux_kernel(float* __restrict__ out, int write) {
    if (threadIdx.x == 0 && write) {
        float l = 0.f;
        for (int e = 0; e < E_NUM; e++)
            l += (d_me[e] / (float)S_TOK) * ((float)d_ce[e] / (float)S_TOK);
        out[(size_t)S_TOK * M_DIM] = l * (float)E_NUM;
    }
}

// ---------------- launch ----------------
extern "C" void kernel_launch(void* const* d_in, const int* in_sizes, int n_in,
                              void* d_out, int out_size) {
    long long mx = 0;
    for (int i = 0; i < n_in; i++) if ((long long)in_sizes[i] > mx) mx = in_sizes[i];
    long long div = (mx >= 134217728LL) ? 4 : 1;

    const float *x = 0, *fc1_b = 0;
    const float* big[2] = {0, 0};
    const float* sml[2] = {0, 0};
    int nbig = 0, nsml = 0;
    for (int i = 0; i < n_in; i++) {
        const float* p = (const float*)d_in[i];
        long long n = (long long)in_sizes[i] / div;
        if (n == (long long)S_TOK * M_DIM) x = p;
        else if (n == (long long)E_NUM * H_DIM) fc1_b = p;
        else if (n == (long long)E_NUM * M_DIM * H_DIM) { if (nbig < 2) big[nbig++] = p; }
        else if (n == (long long)M_DIM * E_NUM) { if (nsml < 2) sml[nsml++] = p; }
    }
    if (!x || !fc1_b || nbig < 2 || nsml < 2) {
        x = (const float*)d_in[0];
        sml[0] = (const float*)d_in[1];
        big[0] = (const float*)d_in[2];
        fc1_b = (const float*)d_in[3];
        big[1] = (const float*)d_in[4];
        sml[1] = (const float*)d_in[5];
    }
    float* out = (float*)d_out;

    const int SMEM_DYN = 3 * STAGE_B;  // 156672 B
    cudaFuncSetAttribute(gemm_mma<1>, cudaFuncAttributeMaxDynamicSharedMemorySize, SMEM_DYN);
    cudaFuncSetAttribute(gemm_mma<2>, cudaFuncAttributeMaxDynamicSharedMemorySize, SMEM_DYN);

    select_kernel<<<1, 32>>>(x, fc1_b, sml[0], sml[1], big[0], big[1]);
    gate_kernel<<<S_TOK / 8, 256>>>();
    me_kernel<<<E_NUM, 256>>>();
    route_kernel<<<1, 256>>>();

    {
        dim3 g(H_DIM / 256, C_CAP / 128, E_NUM);  // (16, 8, 8)
        gemm_mma<1><<<g, 256, SMEM_DYN>>>();
    }
    {
        dim3 g(M_DIM / 256, C_CAP / 128, E_NUM);  // (4, 8, 8)
        gemm_mma<2><<<g, 256, SMEM_DYN>>>();
    }

    combine_kernel<<<S_TOK, 256>>>(out);
    laux_kernel<<<1, 32>>>(out, out_size > S_TOK * M_DIM ? 1 : 0);
}

// round 14
// speedup vs baseline: 1.1231x; 1.0162x over previous
#include <cuda_runtime.h>
#include <cuda_bf16.h>
#include <math.h>
#include <stdint.h>

#define S_TOK 4096
#define M_DIM 1024
#define H_DIM 4096
#define E_NUM 8
#define C_CAP 1024
#define KTOP  2

// ---------------- scratch (__device__ globals; referenced ONLY from device code) ----------------
__device__ float d_xr[(size_t)S_TOK * M_DIM];                 // tf32-rounded x
__device__ float d_h[(size_t)E_NUM * C_CAP * H_DIM];          // tf32-rounded activations
__device__ float d_yo[(size_t)E_NUM * C_CAP * M_DIM];
__device__ float d_scores[S_TOK * E_NUM];
__device__ int   d_topk[S_TOK * KTOP];
__device__ float d_gate[S_TOK * KTOP];
__device__ int   d_flat[S_TOK * KTOP];
__device__ int   d_perm[E_NUM * C_CAP];
__device__ float d_me[E_NUM];
__device__ int   d_ce[E_NUM];

__device__ const float* g_x;
__device__ const float* g_wg;
__device__ const float* g_fc1w;
__device__ const float* g_fc1b;
__device__ const float* g_fc2w;
__device__ const float* g_fc2b;

// ---------------- generic-PTX helpers (sm_80+; valid on compute_103) ----------------
__device__ __forceinline__ uint32_t smem_u32(const void* p) {
    uint32_t a;
    asm("{ .reg .u64 t; cvta.to.shared.u64 t, %1; cvt.u32.u64 %0, t; }" : "=r"(a) : "l"(p));
    return a;
}
__device__ __forceinline__ void cpa16(uint32_t dst, const void* src, int src_bytes) {
    asm volatile("cp.async.cg.shared.global [%0], [%1], 16, %2;"
                 :: "r"(dst), "l"(src), "r"(src_bytes) : "memory");
}
#define CP_COMMIT() asm volatile("cp.async.commit_group;" ::: "memory")
#define CP_WAIT(n)  asm volatile("cp.async.wait_group %0;" :: "n"(n) : "memory")
#define LDSM4(r0, r1, r2, r3, addr)                                        \
    asm volatile("ldmatrix.sync.aligned.m8n8.x4.shared.b16 {%0,%1,%2,%3}, [%4];" \
                 : "=r"(r0), "=r"(r1), "=r"(r2), "=r"(r3) : "r"(addr))
#define MMA16808(d, a, b0, b1)                                             \
    asm volatile("mma.sync.aligned.m16n8k8.row.col.f32.tf32.tf32.f32 "     \
                 "{%0,%1,%2,%3}, {%4,%5,%6,%7}, {%8,%9}, {%0,%1,%2,%3};"   \
                 : "+f"((d)[0]), "+f"((d)[1]), "+f"((d)[2]), "+f"((d)[3])  \
                 : "r"((a)[0]), "r"((a)[1]), "r"((a)[2]), "r"((a)[3]),     \
                   "r"(b0), "r"(b1))
__device__ __forceinline__ uint32_t to_tf32(float v) {
    uint32_t r;
    asm("cvt.rna.tf32.f32 %0, %1;" : "=r"(r) : "f"(v));
    return r;
}
__device__ __forceinline__ uint32_t lds_tf32(uint32_t addr) {
    float v;
    asm volatile("ld.shared.f32 %0, [%1];" : "=f"(v) : "r"(addr));
    return to_tf32(v);
}

// ---------------- select: resolve ambiguous inputs by content ----------------
__global__ __launch_bounds__(32) void select_kernel(
    const float* x, const float* fc1b,
    const float* s0, const float* s1,
    const float* b0, const float* b1) {
    int lane = threadIdx.x;
    float sa = 0.f, sb = 0.f, ca = 0.f, cb = 0.f;
    for (int i = lane; i < 8192; i += 32) {
        sa += fabsf(s0[i]);
        sb += fabsf(s1[i]);
        ca += fabsf(b0[i]);
        cb += fabsf(b1[i]);
    }
    #pragma unroll
    for (int off = 16; off; off >>= 1) {
        sa += __shfl_down_sync(0xffffffffu, sa, off);
        sb += __shfl_down_sync(0xffffffffu, sb, off);
        ca += __shfl_down_sync(0xffffffffu, ca, off);
        cb += __shfl_down_sync(0xffffffffu, cb, off);
    }
    if (lane == 0) {
        g_x = x;
        g_fc1b = fc1b;
        if (sa >= sb) { g_wg = s0; g_fc2b = s1; }
        else          { g_wg = s1; g_fc2b = s0; }
        if (ca >= cb) { g_fc1w = b0; g_fc2w = b1; }
        else          { g_fc1w = b1; g_fc2w = b0; }
        for (int e = 0; e < E_NUM; e++) d_ce[e] = 0;
    }
}

// ---------------- round x to tf32 (vectorized) ----------------
__global__ __launch_bounds__(256) void round_x_kernel() {
    size_t i4 = (size_t)blockIdx.x * 256 + threadIdx.x;
    float4 v = ((const float4*)g_x)[i4];
    uint4 o;
    o.x = to_tf32(v.x);
    o.y = to_tf32(v.y);
    o.z = to_tf32(v.z);
    o.w = to_tf32(v.w);
    ((uint4*)d_xr)[i4] = o;
}

// ---------------- gating: one warp per token ----------------
__global__ __launch_bounds__(256) void gate_kernel() {
    const int warp = threadIdx.x >> 5;
    const int lane = threadIdx.x & 31;
    const int s = blockIdx.x * 8 + warp;
    if (s >= S_TOK) return;
    const float* x = g_x;
    const float* wg = g_wg;

    float acc[E_NUM] = {0.f, 0.f, 0.f, 0.f, 0.f, 0.f, 0.f, 0.f};
    const float* xrow = x + (size_t)s * M_DIM;
    for (int k = lane; k < M_DIM; k += 32) {
        float xv = xrow[k];
        const float4* w = (const float4*)(wg + (size_t)k * E_NUM);
        float4 w0 = w[0], w1 = w[1];
        acc[0] += xv * w0.x; acc[1] += xv * w0.y; acc[2] += xv * w0.z; acc[3] += xv * w0.w;
        acc[4] += xv * w1.x; acc[5] += xv * w1.y; acc[6] += xv * w1.z; acc[7] += xv * w1.w;
    }
    #pragma unroll
    for (int off = 16; off; off >>= 1) {
        #pragma unroll
        for (int e = 0; e < E_NUM; e++)
            acc[e] += __shfl_down_sync(0xffffffffu, acc[e], off);
    }
    if (lane == 0) {
        float mx = acc[0];
        #pragma unroll
        for (int e = 1; e < E_NUM; e++) mx = fmaxf(mx, acc[e]);
        float sum = 0.f, sc[E_NUM];
        #pragma unroll
        for (int e = 0; e < E_NUM; e++) { sc[e] = expf(acc[e] - mx); sum += sc[e]; }
        float inv = 1.f / sum;
        #pragma unroll
        for (int e = 0; e < E_NUM; e++) { sc[e] *= inv; d_scores[s * E_NUM + e] = sc[e]; }
        int id0 = 0;
        #pragma unroll
        for (int e = 1; e < E_NUM; e++) if (sc[e] > sc[id0]) id0 = e;
        int id1 = -1;
        float b1 = -1.f;
        #pragma unroll
        for (int e = 0; e < E_NUM; e++) {
            if (e != id0 && sc[e] > b1) { b1 = sc[e]; id1 = e; }
        }
        if (id1 < 0) id1 = (id0 + 1) & 7;
        float v0 = sc[id0], v1 = sc[id1];
        float denom = fmaxf(v0 + v1, 1e-7f);
        d_topk[s * 2 + 0] = id0;
        d_topk[s * 2 + 1] = id1;
        d_gate[s * 2 + 0] = v0 / denom;
        d_gate[s * 2 + 1] = v1 / denom;
        atomicAdd(&d_ce[id0], 1);
    }
}

// ---------------- me[e] ----------------
__global__ __launch_bounds__(256) void me_kernel() {
    int e = blockIdx.x;
    int tid = threadIdx.x;
    float acc = 0.f;
    for (int s = tid; s < S_TOK; s += 256) acc += d_scores[s * E_NUM + e];
    __shared__ float sm[256];
    sm[tid] = acc;
    __syncthreads();
    for (int d = 128; d; d >>= 1) {
        if (tid < d) sm[tid] += sm[tid + d];
        __syncthreads();
    }
    if (tid == 0) d_me[e] = sm[0];
}

// ---- routing: two-level scan (histogram -> prefix -> place); token-ordered, deterministic ----
// Position order for the prefix is phase-major (all k=0 chunks, then k=1), which
// reproduces the reference's offset carry from phase 0 into phase 1.
#define NCHUNK 128   // 4096 tokens / 32 per chunk
__global__ __launch_bounds__(256) void route_kernel() {
    const int tid = threadIdx.x;
    const int lane = tid & 31;
    const int wid = tid >> 5;
    __shared__ int stopk[S_TOK * KTOP];              // 32 KB
    __shared__ int scnt[KTOP][E_NUM][NCHUNK];        // 8 KB
    __shared__ int sbase[KTOP][E_NUM][NCHUNK];       // 8 KB

    for (int i = tid; i < E_NUM * C_CAP; i += 256) d_perm[i] = -1;
    for (int i = tid; i < S_TOK * KTOP; i += 256) stopk[i] = d_topk[i];
    __syncthreads();

    const int p = tid >> 7;           // phase 0/1
    const int chunk = tid & 127;      // 32-token chunk
    // Stage 1: per-(phase, chunk) expert histogram
    {
        int cnt[E_NUM];
        #pragma unroll
        for (int e = 0; e < E_NUM; e++) cnt[e] = 0;
        #pragma unroll 4
        for (int j = 0; j < 32; j++) {
            int e = stopk[(chunk * 32 + j) * 2 + p];
            e = (e < 0) ? 0 : ((e > 7) ? 7 : e);
            #pragma unroll
            for (int ee = 0; ee < E_NUM; ee++) cnt[ee] += (e == ee);
        }
        #pragma unroll
        for (int e = 0; e < E_NUM; e++) scnt[p][e][chunk] = cnt[e];
    }
    __syncthreads();

    // Stage 2: per-expert exclusive prefix over 256 phase-major positions (warp w = expert w)
    {
        const int e = wid;
        int v[8], pre[8], run = 0;
        #pragma unroll
        for (int j = 0; j < 8; j++) {
            int idx = lane * 8 + j;           // 0..255, phase-major
            v[j] = scnt[idx >> 7][e][idx & 127];
            pre[j] = run;
            run += v[j];
        }
        // warp exclusive scan of per-lane totals
        int lb = run;
        #pragma unroll
        for (int off = 1; off < 32; off <<= 1) {
            int t = __shfl_up_sync(0xffffffffu, lb, off);
            if (lane >= off) lb += t;
        }
        lb -= run;                             // exclusive
        #pragma unroll
        for (int j = 0; j < 8; j++) {
            int idx = lane * 8 + j;
            sbase[idx >> 7][e][idx & 127] = lb + pre[j];
        }
    }
    __syncthreads();

    // Stage 3: placement (parallel across all 256 (phase,chunk) threads)
    {
        int run[E_NUM];
        #pragma unroll
        for (int e = 0; e < E_NUM; e++) run[e] = 0;
        #pragma unroll 4
        for (int j = 0; j < 32; j++) {
            int s = chunk * 32 + j;
            int e = stopk[s * 2 + p];
            e = (e < 0) ? 0 : ((e > 7) ? 7 : e);
            int r = 0;
            #pragma unroll
            for (int ee = 0; ee < E_NUM; ee++) {
                if (e == ee) r = run[ee]++;
            }
            int loc = sbase[p][e][chunk] + r;
            bool valid = loc < C_CAP;
            int flat = e * C_CAP + (valid ? loc : (C_CAP - 1));
            d_flat[s * 2 + p] = flat;
            if (valid) d_perm[flat] = s;
            else       d_gate[s * 2 + p] = 0.f;
        }
    }
}

// -------- tf32 GEMM, block 128x256, 256 threads / 8 warps (warp 64x64), 3-stage cp.async --------
// A: [m][k] K-major smem (144B rows), PRE-ROUNDED tf32 (d_xr / d_h) -> clean ldsm->MMA chain.
// B: [k][n] smem direct from original weights; fragments via 2 conflict-free LDS + cvt.rna.
#define ROWB_A 144
#define ROWN_B 1056
#define OFF_B  18432              // 128 * 144
#define STAGE_B 52224             // 18432 + 32*1056
template <int PHASE>
__global__ __launch_bounds__(256) void gemm_mma() {
    constexpr int KSEG = (PHASE == 1) ? M_DIM : H_DIM;
    constexpr int NDIM = (PHASE == 1) ? H_DIM : M_DIM;
    constexpr int TPS = KSEG / 32;

    extern __shared__ __align__(16) char smem[];
    __shared__ int sRow[128];

    const int tid = threadIdx.x;
    const int lane = tid & 31;
    const int wid = tid >> 5;
    const int wm = wid >> 2;        // 0..1  (64-row slice)
    const int wn = wid & 3;         // 0..3  (64-col slice)
    const int e = blockIdx.z;
    const int M0 = blockIdx.y * 128;
    const int N0 = blockIdx.x * 256;
    const uint32_t sbase = smem_u32(smem);

    if (PHASE == 1) {
        if (tid < 128) sRow[tid] = d_perm[e * C_CAP + tid + M0];
    }
    __syncthreads();

    const float* A = (PHASE == 1) ? d_xr : d_h;        // pre-rounded tf32
    const float* W = (PHASE == 1) ? g_fc1w : g_fc2w;   // [e][k][n], raw fp32

    auto issue_stage = [&](int stg, int kt) {
        const int kb = kt * 32;
        uint32_t base = sbase + stg * STAGE_B;
        #pragma unroll
        for (int i = 0; i < 4; i++) {       // A: 128 rows x 8 chunks(16B)
            int ch = tid + i * 256, r = ch >> 3, c = ch & 7;
            size_t srcoff;
            int bytes = 16;
            if (PHASE == 1) {
                int sr = sRow[r];
                srcoff = (sr >= 0) ? ((size_t)sr * KSEG + kb + c * 4) : 0;
                if (sr < 0) bytes = 0;
            } else {
                srcoff = (size_t)(e * C_CAP + M0 + r) * KSEG + kb + c * 4;
            }
            cpa16(base + r * ROWB_A + c * 16, A + srcoff, bytes);
        }
        #pragma unroll
        for (int i = 0; i < 8; i++) {       // B: 32 k-rows x 64 chunks(16B)
            int ch = tid + i * 256, r = ch >> 6, c = ch & 63;
            size_t srcoff = (size_t)e * KSEG * NDIM + (size_t)(kb + r) * NDIM + N0 + c * 4;
            cpa16(base + OFF_B + r * ROWN_B + c * 16, W + srcoff, 16);
        }
    };

    float acc[4][8][4];
    #pragma unroll
    for (int mi = 0; mi < 4; mi++)
        #pragma unroll
        for (int ni = 0; ni < 8; ni++)
            #pragma unroll
            for (int q = 0; q < 4; q++) acc[mi][ni][q] = 0.f;

    const int l_r = lane & 15;
    const int l_c = (lane >> 4) * 16;
    const int bq = lane >> 2;       // n offset within n8 block
    const int br = lane & 3;        // k offset within k8 block

    issue_stage(0, 0);
    CP_COMMIT();
    issue_stage(1, 1);
    CP_COMMIT();

    for (int it = 0; it < TPS; it++) {
        if (it + 1 < TPS) CP_WAIT(1);
        else              CP_WAIT(0);
        __syncthreads();

        if (it + 2 < TPS) { issue_stage((it + 2) % 3, it + 2); CP_COMMIT(); }

        uint32_t base = sbase + (it % 3) * STAGE_B;
        #pragma unroll
        for (int kk = 0; kk < 4; kk++) {    // four k8 steps per k32 stage
            // A fragments: 4 m16-blocks via ldsm.x4 (tf32-as-b16-pairs trick)
            uint32_t af[4][4];
            #pragma unroll
            for (int mi = 0; mi < 4; mi++) {
                uint32_t ad = base + (uint32_t)(wm * 64 + mi * 16 + l_r) * ROWB_A
                            + (uint32_t)(kk * 32 + l_c);
                LDSM4(af[mi][0], af[mi][1], af[mi][2], af[mi][3], ad);
            }
            // B fragments from [k][n] tile
            uint32_t bd0 = base + OFF_B + (uint32_t)(kk * 8 + br) * ROWN_B
                         + (uint32_t)(wn * 64 + bq) * 4;
            uint32_t bfr[8][2];
            #pragma unroll
            for (int ni = 0; ni < 8; ni++) {
                bfr[ni][0] = lds_tf32(bd0 + ni * 32);
                bfr[ni][1] = lds_tf32(bd0 + ni * 32 + 4 * ROWN_B);
            }
            #pragma unroll
            for (int mi = 0; mi < 4; mi++)
                #pragma unroll
                for (int ni = 0; ni < 8; ni++)
                    MMA16808(acc[mi][ni], af[mi], bfr[ni][0], bfr[ni][1]);
        }
    }

    // ---- epilogue ----
    const float* bias = (PHASE == 1) ? g_fc1b : g_fc2b;
    #pragma unroll
    for (int mi = 0; mi < 4; mi++) {
        #pragma unroll
        for (int ni = 0; ni < 8; ni++) {
            int c = N0 + wn * 64 + ni * 8 + (lane & 3) * 2;
            float2 bv = *(const float2*)&bias[(size_t)e * NDIM + c];
            int r0 = M0 + wm * 64 + mi * 16 + (lane >> 2);
            #pragma unroll
            for (int h = 0; h < 2; h++) {
                int rg = r0 + h * 8;
                float v0 = acc[mi][ni][h * 2 + 0] + bv.x;
                float v1 = acc[mi][ni][h * 2 + 1] + bv.y;
                if (PHASE == 1) {
                    v0 = fmaxf(v0, 0.f);
                    v1 = fmaxf(v1, 0.f);
                    uint2 t = make_uint2(to_tf32(v0), to_tf32(v1));
                    size_t o = (size_t)(e * C_CAP + rg) * H_DIM + c;
                    *(uint2*)(d_h + o) = t;
                } else {
                    size_t o = (size_t)(e * C_CAP + rg) * M_DIM + c;
                    *(float2*)(d_yo + o) = make_float2(v0, v1);
                }
            }
        }
    }
}

// ---------------- combine ----------------
__global__ __launch_bounds__(256) void combine_kernel(float* __restrict__ out) {
    int s = blockIdx.x;
    int tid = threadIdx.x;
    int f0 = d_flat[s * 2 + 0];
    int f1 = d_flat[s * 2 + 1];
    float g0 = d_gate[s * 2 + 0];
    float g1 = d_gate[s * 2 + 1];
    float4 a = ((const float4*)(d_yo + (size_t)f0 * M_DIM))[tid];
    float4 b = ((const float4*)(d_yo + (size_t)f1 * M_DIM))[tid];
    float4 o;
    o.x = g0 * a.x + g1 * b.x;
    o.y = g0 * a.y + g1 * b.y;
    o.z = g0 * a.z + g1 * b.z;
    o.w = g0 * a.w + g1 * b.w;
    ((float4*)(out + (size_t)s * M_DIM))[tid] = o;
}

// ---------------- l_aux ----------------
__global__ __launch_bounds__(32) void laux_kernel(float* __restrict__ out, int write) {
    if (threadIdx.x == 0 && write) {
        float l = 0.f;
        for (int e = 0; e < E_NUM; e++)
            l += (d_me[e] / (float)S_TOK) * ((float)d_ce[e] / (float)S_TOK);
        out[(size_t)S_TOK * M_DIM] = l * (float)E_NUM;
    }
}

// ---------------- launch ----------------
extern "C" void kernel_launch(void* const* d_in, const int* in_sizes, int n_in,
                              void* d_out, int out_size) {
    long long mx = 0;
    for (int i = 0; i < n_in; i++) if ((long long)in_sizes[i] > mx) mx = in_sizes[i];
    long long div = (mx >= 134217728LL) ? 4 : 1;

    const float *x = 0, *fc1_b = 0;
    const float* big[2] = {0, 0};
    const float* sml[2] = {0, 0};
    int nbig = 0, nsml = 0;
    for (int i = 0; i < n_in; i++) {
        const float* p = (const float*)d_in[i];
        long long n = (long long)in_sizes[i] / div;
        if (n == (long long)S_TOK * M_DIM) x = p;
        else if (n == (long long)E_NUM * H_DIM) fc1_b = p;
        else if (n == (long long)E_NUM * M_DIM * H_DIM) { if (nbig < 2) big[nbig++] = p; }
        else if (n == (long long)M_DIM * E_NUM) { if (nsml < 2) sml[nsml++] = p; }
    }
    if (!x || !fc1_b || nbig < 2 || nsml < 2) {
        x = (const float*)d_in[0];
        sml[0] = (const float*)d_in[1];
        big[0] = (const float*)d_in[2];
        fc1_b = (const float*)d_in[3];
        big[1] = (const float*)d_in[4];
        sml[1] = (const float*)d_in[5];
    }
    float* out = (float*)d_out;

    const int SMEM_DYN = 3 * STAGE_B;  // 156672 B
    cudaFuncSetAttribute(gemm_mma<1>, cudaFuncAttributeMaxDynamicSharedMemorySize, SMEM_DYN);
    cudaFuncSetAttribute(gemm_mma<2>, cudaFuncAttributeMaxDynamicSharedMemorySize, SMEM_DYN);

    select_kernel<<<1, 32>>>(x, fc1_b, sml[0], sml[1], big[0], big[1]);
    round_x_kernel<<<(S_TOK * M_DIM) / 4 / 256, 256>>>();
    gate_kernel<<<S_TOK / 8, 256>>>();
    me_kernel<<<E_NUM, 256>>>();
    route_kernel<<<1, 256>>>();

    {
        dim3 g(H_DIM / 256, C_CAP / 128, E_NUM);  // (16, 8, 8)
        gemm_mma<1><<<g, 256, SMEM_DYN>>>();
    }
    {
        dim3 g(M_DIM / 256, C_CAP / 128, E_NUM);  // (4, 8, 8)
        gemm_mma<2><<<g, 256, SMEM_DYN>>>();
    }

    combine_kernel<<<S_TOK, 256>>>(out);
    laux_kernel<<<1, 32>>>(out, out_size > S_TOK * M_DIM ? 1 : 0);
}